// round 13
// baseline (speedup 1.0000x reference)
#include <cuda_runtime.h>

// ConvSepKanCell: per-pixel dynamic KAN — float2, 2 outputs/thread, staged coef chunks.
// i-loop split across grid.z=2 (half-length CTAs, better tail/spread); the reduction
// of the two halves is FUSED: second-arriving CTA per tile sums partials and writes out.
// x: (2, 16, 128, 128) f32   w: (2, 3328, 128, 128) f32   out: (2, 16, 128, 128) f32
//   [0, 2816)      coef[i][o][m]  (16 x 16 x 11)
//   [2816, 3072)   uw[i][o]
//   [3072, 3328)   rw[i][o]
// y[o] = sum_i uw[i][o] * (sum_m coef[i][o][m]*B3_m(x_i)) + rw[i][o]*silu(x_i)

#define HW      16384
#define HW2     8192
#define INC     16
#define IHALF   8
#define OUTC    16
#define COEFM   11
#define SIZE_W  3328
#define I0      2816
#define I1      3072
#define OSPLIT  8
#define TPB     128
#define NTILES  (128 * OSPLIT)               // grid.x * grid.y
#define OUT_ELEMS (2 * OUTC * HW)            // 524288 floats per half

__device__ __align__(16) float g_scratch[2 * OUT_ELEMS];   // 4 MB static scratch
__device__ int g_count[NTILES];                            // zero-initialized

__device__ __forceinline__ float2 ldcs2(const float2* p) { return __ldcs(p); }
__device__ __forceinline__ float2 ldcg2(const float2* p) { return __ldcg(p); }

__global__ __launch_bounds__(TPB, 7)
void kan_kernel(const float* __restrict__ x,
                const float* __restrict__ w,
                float* __restrict__ out)
{
    const int t     = blockIdx.x * TPB + threadIdx.x;   // 0..16383 (float2 slots)
    const int slice = blockIdx.y;                       // 0..7
    const int z     = blockIdx.z;                       // 0..1: i-half
    const int b   = t >> 13;
    const int hw2 = t & (HW2 - 1);

    const float2* wp = (const float2*)(w + (size_t)b * SIZE_W * HW) + hw2;
    const float2* xp = (const float2*)(x + (size_t)b * INC * HW) + hw2
                       + (size_t)(z * IHALF) * HW2;

    const float2* cp = wp + (size_t)(slice * 2 * COEFM) * HW2
                          + (size_t)(z * IHALF * OUTC * COEFM) * HW2;
    const float2* up = wp + (size_t)(I0 + slice * 2) * HW2
                          + (size_t)(z * IHALF * OUTC) * HW2;
    const float2* rp = wp + (size_t)(I1 + slice * 2) * HW2
                          + (size_t)(z * IHALF * OUTC) * HW2;

    float y0a = 0.f, y0b = 0.f, y1a = 0.f, y1b = 0.f;

    float2 xi = __ldg(xp);
    xp += HW2;

    for (int i = 0; i < IHALF; ++i) {
        // ---- hoisted independent loads ----
        const float2 u0 = ldcs2(up + 0 * HW2);
        const float2 u1 = ldcs2(up + 1 * HW2);
        const float2 r0 = ldcs2(rp + 0 * HW2);
        const float2 r1 = ldcs2(rp + 1 * HW2);
        float2 xn;
        if (i < IHALF - 1) { xn = __ldg(xp); xp += HW2; }

        // ---- chunk 0 (m = 0..3): issue before basis compute ----
        float2 A0[4], A1[4];
        #pragma unroll
        for (int k = 0; k < 4; ++k) {
            A0[k] = ldcs2(cp + (0 * COEFM + k) * HW2);
            A1[k] = ldcs2(cp + (1 * COEFM + k) * HW2);
        }

        // ---- Cox-de Boor, K=3, uniform knots grid[j] = 0.25j - 1.75 (exact fp32) ----
        float ba[14], bc[14];
        #pragma unroll
        for (int j = 0; j < 14; ++j) {
            const float gj = 0.25f * (float)j - 1.75f;
            ba[j] = (xi.x >= gj && xi.x < gj + 0.25f) ? 1.f : 0.f;
            bc[j] = (xi.y >= gj && xi.y < gj + 0.25f) ? 1.f : 0.f;
        }
        const float ta = fmaf(xi.x, 4.0f, 7.0f);
        const float tc = fmaf(xi.y, 4.0f, 7.0f);
        #pragma unroll
        for (int p = 1; p <= 3; ++p) {
            const float invp = 1.0f / (float)p;
            #pragma unroll
            for (int j = 0; j < 14 - p; ++j) {
                const float la = (ta - (float)j) * invp;
                const float ra = ((float)(j + p + 1) - ta) * invp;
                ba[j] = la * ba[j] + ra * ba[j + 1];
                const float lc = (tc - (float)j) * invp;
                const float rc = ((float)(j + p + 1) - tc) * invp;
                bc[j] = lc * bc[j] + rc * bc[j + 1];
            }
        }
        const float sxa = xi.x / (1.0f + __expf(-xi.x));
        const float sxb = xi.y / (1.0f + __expf(-xi.y));

        float s0a = 0.f, s0b = 0.f, s1a = 0.f, s1b = 0.f;

        // ---- stage 1: issue chunk 1 (m = 4..7), consume chunk 0 ----
        float2 B0[4], B1[4];
        #pragma unroll
        for (int k = 0; k < 4; ++k) {
            B0[k] = ldcs2(cp + (0 * COEFM + 4 + k) * HW2);
            B1[k] = ldcs2(cp + (1 * COEFM + 4 + k) * HW2);
        }
        #pragma unroll
        for (int k = 0; k < 4; ++k) {
            s0a = fmaf(A0[k].x, ba[k], s0a);
            s0b = fmaf(A0[k].y, bc[k], s0b);
            s1a = fmaf(A1[k].x, ba[k], s1a);
            s1b = fmaf(A1[k].y, bc[k], s1b);
        }

        // ---- stage 2: issue chunk 2 (m = 8..10), consume chunk 1 ----
        float2 C0[3], C1[3];
        #pragma unroll
        for (int k = 0; k < 3; ++k) {
            C0[k] = ldcs2(cp + (0 * COEFM + 8 + k) * HW2);
            C1[k] = ldcs2(cp + (1 * COEFM + 8 + k) * HW2);
        }
        #pragma unroll
        for (int k = 0; k < 4; ++k) {
            s0a = fmaf(B0[k].x, ba[4 + k], s0a);
            s0b = fmaf(B0[k].y, bc[4 + k], s0b);
            s1a = fmaf(B1[k].x, ba[4 + k], s1a);
            s1b = fmaf(B1[k].y, bc[4 + k], s1b);
        }

        // ---- stage 3: consume chunk 2 ----
        #pragma unroll
        for (int k = 0; k < 3; ++k) {
            s0a = fmaf(C0[k].x, ba[8 + k], s0a);
            s0b = fmaf(C0[k].y, bc[8 + k], s0b);
            s1a = fmaf(C1[k].x, ba[8 + k], s1a);
            s1b = fmaf(C1[k].y, bc[8 + k], s1b);
        }

        y0a += u0.x * s0a + r0.x * sxa;
        y0b += u0.y * s0b + r0.y * sxb;
        y1a += u1.x * s1a + r1.x * sxa;
        y1b += u1.y * s1b + r1.y * sxb;

        xi = xn;
        cp += (size_t)(OUTC * COEFM) * HW2;
        up += (size_t)OUTC * HW2;
        rp += (size_t)OUTC * HW2;
    }

    // ---- publish partials for this half ----
    const size_t ooff = (size_t)b * OUTC * HW2 + (size_t)(slice * 2) * HW2 + hw2;
    float2* sp = (float2*)(g_scratch + (size_t)z * OUT_ELEMS) + ooff;
    sp[0 * HW2] = make_float2(y0a, y0b);
    sp[1 * HW2] = make_float2(y1a, y1b);

    // ---- retirement: second CTA per tile fuses the reduction ----
    __threadfence();
    __syncthreads();

    __shared__ int s_last;
    if (threadIdx.x == 0) {
        const int tile = blockIdx.y * gridDim.x + blockIdx.x;
        const int old = atomicAdd(&g_count[tile], 1);
        s_last = (old == 1);
        if (old == 1) g_count[tile] = 0;     // reset for next graph replay
    }
    __syncthreads();

    if (s_last) {
        __threadfence();                      // acquire: other half's stores visible
        const float2* osp = (const float2*)(g_scratch + (size_t)(z ^ 1) * OUT_ELEMS) + ooff;
        const float2 o0 = ldcg2(osp + 0 * HW2);
        const float2 o1 = ldcg2(osp + 1 * HW2);
        float2* op = (float2*)out + ooff;
        op[0 * HW2] = make_float2(o0.x + y0a, o0.y + y0b);
        op[1 * HW2] = make_float2(o1.x + y1a, o1.y + y1b);
    }
}

extern "C" void kernel_launch(void* const* d_in, const int* in_sizes, int n_in,
                              void* d_out, int out_size)
{
    const float* x = (const float*)d_in[0];
    const float* w = (const float*)d_in[1];
    float* out = (float*)d_out;

    dim3 grid(16384 / TPB, OSPLIT, 2);   // (128, 8, 2) = 2048 half-length CTAs
    kan_kernel<<<grid, TPB>>>(x, w, out);
}

// round 14
// speedup vs baseline: 1.0262x; 1.0262x over previous
#include <cuda_runtime.h>

// ConvSepKanCell: per-pixel dynamic KAN — float2 (2 pixels/thread), 2 outputs/thread.
// Software-pipelined: u/r hoisted, x prefetched 1 iter ahead, coef stream staged in
// 3 double-buffered chunks. Grid dims swapped to (slice, pixel-chunk) so the resident
// CTA wave spreads across all 8 slices' plane sets (wider HBM page/channel spread).
// x: (2, 16, 128, 128) f32   w: (2, 3328, 128, 128) f32   out: (2, 16, 128, 128) f32
//   [0, 2816)      coef[i][o][m]  (16 x 16 x 11)
//   [2816, 3072)   uw[i][o]
//   [3072, 3328)   rw[i][o]
// y[o] = sum_i uw[i][o] * (sum_m coef[i][o][m]*B3_m(x_i)) + rw[i][o]*silu(x_i)

#define HW      16384
#define HW2     8192      // float2 elements per image plane
#define INC     16
#define OUTC    16
#define COEFM   11
#define SIZE_W  3328
#define I0      2816
#define I1      3072
#define OSPLIT  8         // outputs per thread = 2
#define TPB     128

__device__ __forceinline__ float2 ldcs2(const float2* p) { return __ldcs(p); }

__global__ __launch_bounds__(TPB, 7)
void kan_kernel(const float* __restrict__ x,
                const float* __restrict__ w,
                float* __restrict__ out)
{
    const int t     = blockIdx.y * TPB + threadIdx.x;   // 0..16383 (float2 slots)
    const int slice = blockIdx.x;                       // 0..7 -> outputs slice*2..+2
    const int b   = t >> 13;
    const int hw2 = t & (HW2 - 1);

    const float2* wp = (const float2*)(w + (size_t)b * SIZE_W * HW) + hw2;
    const float2* xp = (const float2*)(x + (size_t)b * INC * HW) + hw2;

    const float2* cp = wp + (size_t)(slice * 2 * COEFM) * HW2;
    const float2* up = wp + (size_t)(I0 + slice * 2) * HW2;
    const float2* rp = wp + (size_t)(I1 + slice * 2) * HW2;

    float y0a = 0.f, y0b = 0.f, y1a = 0.f, y1b = 0.f;

    float2 xi = __ldg(xp);           // x for iteration 0
    xp += HW2;

    for (int i = 0; i < INC; ++i) {
        // ---- hoisted independent loads: u/r for this iter, x for next iter ----
        const float2 u0 = ldcs2(up + 0 * HW2);
        const float2 u1 = ldcs2(up + 1 * HW2);
        const float2 r0 = ldcs2(rp + 0 * HW2);
        const float2 r1 = ldcs2(rp + 1 * HW2);
        float2 xn;
        if (i < INC - 1) { xn = __ldg(xp); xp += HW2; }

        // ---- chunk 0 of coef stream (m = 0..3): issue before basis compute ----
        float2 A0[4], A1[4];
        #pragma unroll
        for (int k = 0; k < 4; ++k) {
            A0[k] = ldcs2(cp + (0 * COEFM + k) * HW2);
            A1[k] = ldcs2(cp + (1 * COEFM + k) * HW2);
        }

        // ---- Cox-de Boor, K=3, uniform knots grid[j] = 0.25j - 1.75 (exact fp32) ----
        float ba[14], bc[14];
        #pragma unroll
        for (int j = 0; j < 14; ++j) {
            const float gj = 0.25f * (float)j - 1.75f;
            ba[j] = (xi.x >= gj && xi.x < gj + 0.25f) ? 1.f : 0.f;
            bc[j] = (xi.y >= gj && xi.y < gj + 0.25f) ? 1.f : 0.f;
        }
        const float ta = fmaf(xi.x, 4.0f, 7.0f);
        const float tc = fmaf(xi.y, 4.0f, 7.0f);
        #pragma unroll
        for (int p = 1; p <= 3; ++p) {
            const float invp = 1.0f / (float)p;
            #pragma unroll
            for (int j = 0; j < 14 - p; ++j) {
                const float la = (ta - (float)j) * invp;
                const float ra = ((float)(j + p + 1) - ta) * invp;
                ba[j] = la * ba[j] + ra * ba[j + 1];
                const float lc = (tc - (float)j) * invp;
                const float rc = ((float)(j + p + 1) - tc) * invp;
                bc[j] = lc * bc[j] + rc * bc[j + 1];
            }
        }
        const float sxa = xi.x / (1.0f + __expf(-xi.x));
        const float sxb = xi.y / (1.0f + __expf(-xi.y));

        float s0a = 0.f, s0b = 0.f, s1a = 0.f, s1b = 0.f;

        // ---- stage 1: issue chunk 1 (m = 4..7), consume chunk 0 ----
        float2 B0[4], B1[4];
        #pragma unroll
        for (int k = 0; k < 4; ++k) {
            B0[k] = ldcs2(cp + (0 * COEFM + 4 + k) * HW2);
            B1[k] = ldcs2(cp + (1 * COEFM + 4 + k) * HW2);
        }
        #pragma unroll
        for (int k = 0; k < 4; ++k) {
            s0a = fmaf(A0[k].x, ba[k], s0a);
            s0b = fmaf(A0[k].y, bc[k], s0b);
            s1a = fmaf(A1[k].x, ba[k], s1a);
            s1b = fmaf(A1[k].y, bc[k], s1b);
        }

        // ---- stage 2: issue chunk 2 (m = 8..10), consume chunk 1 ----
        float2 C0[3], C1[3];
        #pragma unroll
        for (int k = 0; k < 3; ++k) {
            C0[k] = ldcs2(cp + (0 * COEFM + 8 + k) * HW2);
            C1[k] = ldcs2(cp + (1 * COEFM + 8 + k) * HW2);
        }
        #pragma unroll
        for (int k = 0; k < 4; ++k) {
            s0a = fmaf(B0[k].x, ba[4 + k], s0a);
            s0b = fmaf(B0[k].y, bc[4 + k], s0b);
            s1a = fmaf(B1[k].x, ba[4 + k], s1a);
            s1b = fmaf(B1[k].y, bc[4 + k], s1b);
        }

        // ---- stage 3: consume chunk 2 ----
        #pragma unroll
        for (int k = 0; k < 3; ++k) {
            s0a = fmaf(C0[k].x, ba[8 + k], s0a);
            s0b = fmaf(C0[k].y, bc[8 + k], s0b);
            s1a = fmaf(C1[k].x, ba[8 + k], s1a);
            s1b = fmaf(C1[k].y, bc[8 + k], s1b);
        }

        y0a += u0.x * s0a + r0.x * sxa;
        y0b += u0.y * s0b + r0.y * sxb;
        y1a += u1.x * s1a + r1.x * sxa;
        y1b += u1.y * s1b + r1.y * sxb;

        xi = xn;
        cp += (size_t)(OUTC * COEFM) * HW2;
        up += (size_t)OUTC * HW2;
        rp += (size_t)OUTC * HW2;
    }

    float2* op = (float2*)(out + (size_t)b * OUTC * HW) + (size_t)(slice * 2) * HW2 + hw2;
    op[0 * HW2] = make_float2(y0a, y0b);
    op[1 * HW2] = make_float2(y1a, y1b);
}

extern "C" void kernel_launch(void* const* d_in, const int* in_sizes, int n_in,
                              void* d_out, int out_size)
{
    const float* x = (const float*)d_in[0];
    const float* w = (const float*)d_in[1];
    float* out = (float*)d_out;

    dim3 grid(OSPLIT, 16384 / TPB);   // (8, 128): consecutive bids span all slices
    kan_kernel<<<grid, TPB>>>(x, w, out);
}

// round 15
// speedup vs baseline: 1.0369x; 1.0104x over previous
#include <cuda_runtime.h>

// ConvSepKanCell: per-pixel dynamic KAN — float2 (2 pixels/thread), 2 outputs/thread.
// Software-pipelined: u/r hoisted, x prefetched 1 iter ahead, coef stream staged in
// 3 double-buffered register chunks; streaming (__ldcs) reads of the read-once w
// stream and streaming (__stcs) output stores. Grid (pixel-chunk, slice) = (128, 8).
// x: (2, 16, 128, 128) f32   w: (2, 3328, 128, 128) f32   out: (2, 16, 128, 128) f32
//   [0, 2816)      coef[i][o][m]  (16 x 16 x 11)
//   [2816, 3072)   uw[i][o]
//   [3072, 3328)   rw[i][o]
// y[o] = sum_i uw[i][o] * (sum_m coef[i][o][m]*B3_m(x_i)) + rw[i][o]*silu(x_i)

#define HW      16384
#define HW2     8192      // float2 elements per image plane
#define INC     16
#define OUTC    16
#define COEFM   11
#define SIZE_W  3328
#define I0      2816
#define I1      3072
#define OSPLIT  8         // outputs per thread = 2
#define TPB     128

__device__ __forceinline__ float2 ldcs2(const float2* p) { return __ldcs(p); }

__global__ __launch_bounds__(TPB, 7)
void kan_kernel(const float* __restrict__ x,
                const float* __restrict__ w,
                float* __restrict__ out)
{
    const int t     = blockIdx.x * TPB + threadIdx.x;   // 0..16383 (float2 slots)
    const int slice = blockIdx.y;                       // 0..7 -> outputs slice*2..+2
    const int b   = t >> 13;
    const int hw2 = t & (HW2 - 1);

    const float2* wp = (const float2*)(w + (size_t)b * SIZE_W * HW) + hw2;
    const float2* xp = (const float2*)(x + (size_t)b * INC * HW) + hw2;

    const float2* cp = wp + (size_t)(slice * 2 * COEFM) * HW2;
    const float2* up = wp + (size_t)(I0 + slice * 2) * HW2;
    const float2* rp = wp + (size_t)(I1 + slice * 2) * HW2;

    float y0a = 0.f, y0b = 0.f, y1a = 0.f, y1b = 0.f;

    float2 xi = __ldg(xp);           // x for iteration 0
    xp += HW2;

    for (int i = 0; i < INC; ++i) {
        // ---- hoisted independent loads: u/r for this iter, x for next iter ----
        const float2 u0 = ldcs2(up + 0 * HW2);
        const float2 u1 = ldcs2(up + 1 * HW2);
        const float2 r0 = ldcs2(rp + 0 * HW2);
        const float2 r1 = ldcs2(rp + 1 * HW2);
        float2 xn;
        if (i < INC - 1) { xn = __ldg(xp); xp += HW2; }

        // ---- chunk 0 of coef stream (m = 0..3): issue before basis compute ----
        float2 A0[4], A1[4];
        #pragma unroll
        for (int k = 0; k < 4; ++k) {
            A0[k] = ldcs2(cp + (0 * COEFM + k) * HW2);
            A1[k] = ldcs2(cp + (1 * COEFM + k) * HW2);
        }

        // ---- Cox-de Boor, K=3, uniform knots grid[j] = 0.25j - 1.75 (exact fp32) ----
        float ba[14], bc[14];
        #pragma unroll
        for (int j = 0; j < 14; ++j) {
            const float gj = 0.25f * (float)j - 1.75f;
            ba[j] = (xi.x >= gj && xi.x < gj + 0.25f) ? 1.f : 0.f;
            bc[j] = (xi.y >= gj && xi.y < gj + 0.25f) ? 1.f : 0.f;
        }
        const float ta = fmaf(xi.x, 4.0f, 7.0f);
        const float tc = fmaf(xi.y, 4.0f, 7.0f);
        #pragma unroll
        for (int p = 1; p <= 3; ++p) {
            const float invp = 1.0f / (float)p;
            #pragma unroll
            for (int j = 0; j < 14 - p; ++j) {
                const float la = (ta - (float)j) * invp;
                const float ra = ((float)(j + p + 1) - ta) * invp;
                ba[j] = la * ba[j] + ra * ba[j + 1];
                const float lc = (tc - (float)j) * invp;
                const float rc = ((float)(j + p + 1) - tc) * invp;
                bc[j] = lc * bc[j] + rc * bc[j + 1];
            }
        }
        const float sxa = xi.x / (1.0f + __expf(-xi.x));
        const float sxb = xi.y / (1.0f + __expf(-xi.y));

        float s0a = 0.f, s0b = 0.f, s1a = 0.f, s1b = 0.f;

        // ---- stage 1: issue chunk 1 (m = 4..7), consume chunk 0 ----
        float2 B0[4], B1[4];
        #pragma unroll
        for (int k = 0; k < 4; ++k) {
            B0[k] = ldcs2(cp + (0 * COEFM + 4 + k) * HW2);
            B1[k] = ldcs2(cp + (1 * COEFM + 4 + k) * HW2);
        }
        #pragma unroll
        for (int k = 0; k < 4; ++k) {
            s0a = fmaf(A0[k].x, ba[k], s0a);
            s0b = fmaf(A0[k].y, bc[k], s0b);
            s1a = fmaf(A1[k].x, ba[k], s1a);
            s1b = fmaf(A1[k].y, bc[k], s1b);
        }

        // ---- stage 2: issue chunk 2 (m = 8..10), consume chunk 1 ----
        float2 C0[3], C1[3];
        #pragma unroll
        for (int k = 0; k < 3; ++k) {
            C0[k] = ldcs2(cp + (0 * COEFM + 8 + k) * HW2);
            C1[k] = ldcs2(cp + (1 * COEFM + 8 + k) * HW2);
        }
        #pragma unroll
        for (int k = 0; k < 4; ++k) {
            s0a = fmaf(B0[k].x, ba[4 + k], s0a);
            s0b = fmaf(B0[k].y, bc[4 + k], s0b);
            s1a = fmaf(B1[k].x, ba[4 + k], s1a);
            s1b = fmaf(B1[k].y, bc[4 + k], s1b);
        }

        // ---- stage 3: consume chunk 2 ----
        #pragma unroll
        for (int k = 0; k < 3; ++k) {
            s0a = fmaf(C0[k].x, ba[8 + k], s0a);
            s0b = fmaf(C0[k].y, bc[8 + k], s0b);
            s1a = fmaf(C1[k].x, ba[8 + k], s1a);
            s1b = fmaf(C1[k].y, bc[8 + k], s1b);
        }

        y0a += u0.x * s0a + r0.x * sxa;
        y0b += u0.y * s0b + r0.y * sxb;
        y1a += u1.x * s1a + r1.x * sxa;
        y1b += u1.y * s1b + r1.y * sxb;

        xi = xn;
        cp += (size_t)(OUTC * COEFM) * HW2;
        up += (size_t)OUTC * HW2;
        rp += (size_t)OUTC * HW2;
    }

    float2* op = (float2*)(out + (size_t)b * OUTC * HW) + (size_t)(slice * 2) * HW2 + hw2;
    __stcs(op + 0 * HW2, make_float2(y0a, y0b));   // streaming store: output never re-read
    __stcs(op + 1 * HW2, make_float2(y1a, y1b));
}

extern "C" void kernel_launch(void* const* d_in, const int* in_sizes, int n_in,
                              void* d_out, int out_size)
{
    const float* x = (const float*)d_in[0];
    const float* w = (const float*)d_in[1];
    float* out = (float*)d_out;

    dim3 grid(16384 / TPB, OSPLIT);   // (128, 8) = 1024 blocks of 128 threads
    kan_kernel<<<grid, TPB>>>(x, w, out);
}